// round 2
// baseline (speedup 1.0000x reference)
#include <cuda_runtime.h>
#include <cuda_bf16.h>

// Problem constants
#define HFEAT 72
#define CFEAT 256
#define MDIM  (HFEAT * HFEAT)   // 5184
#define KDIM  CFEAT             // 256
#define OUTH  224
#define OUTW  224

// GEMM tiling
#define BM 64
#define BN 64
#define BK 32

// Scratch (no cudaMalloc allowed): row/col relu-sums + global max bits
__device__ float        g_rowsum[MDIM];
__device__ float        g_colsum[MDIM];
__device__ unsigned int g_maxbits;

// Order-preserving float<->uint mapping (handles negatives) for atomicMax
__device__ __forceinline__ unsigned int f2u_mono(float f) {
    unsigned int b = __float_as_uint(f);
    return (b & 0x80000000u) ? ~b : (b | 0x80000000u);
}
__device__ __forceinline__ float u2f_mono(unsigned int u) {
    unsigned int b = (u & 0x80000000u) ? (u & 0x7FFFFFFFu) : ~u;
    return __uint_as_float(b);
}

__global__ void simcam_init_kernel() {
    int i = blockIdx.x * blockDim.x + threadIdx.x;
    if (i < MDIM) {
        g_rowsum[i] = 0.0f;
        g_colsum[i] = 0.0f;
    }
    if (i == 0) g_maxbits = 0u;  // decodes below any real float's mapped value
}

// Fused GEMM + streaming reductions.
// A: [MDIM, KDIM] row-major (x[0] flattened), B: [MDIM, KDIM] (x[1] flattened)
// G = A * B^T. Per 64x64 tile: accumulate relu row-sums -> g_rowsum,
// relu col-sums -> g_colsum, and running max (pre-relu) -> g_maxbits.
__global__ __launch_bounds__(256) void simcam_gemm_reduce_kernel(
    const float* __restrict__ A, const float* __restrict__ B)
{
    __shared__ float As[BK][BM + 1];
    __shared__ float Bs[BK][BN + 1];
    __shared__ float rowRed[BM];
    __shared__ float colRed[BN];
    __shared__ unsigned int smaxu;

    const int tid = threadIdx.x;
    const int tx = tid & 15;       // 0..15 (col group)
    const int ty = tid >> 4;       // 0..15 (row group)
    const int rowBase = blockIdx.y * BM;
    const int colBase = blockIdx.x * BN;

    // float4 views of the two 64-row operand panels (KDIM=256 -> 64 float4/row)
    const float4* __restrict__ A4 = (const float4*)(A + rowBase * KDIM);
    const float4* __restrict__ B4 = (const float4*)(B + colBase * KDIM);

    float acc[4][4] = {};

    for (int k0 = 0; k0 < KDIM; k0 += BK) {
        const int kq0 = k0 >> 2;  // float4 offset of this k-chunk within a row
        // Load 64x32 tiles of A and B (transposed into smem: [k][row]).
        // 512 float4 per matrix; 256 threads -> 2 each.
        #pragma unroll
        for (int it = 0; it < 2; it++) {
            int idx = tid + it * 256;     // 0..511
            int r  = idx >> 3;            // 0..63
            int kq = idx & 7;             // 0..7  (k = kq*4 .. kq*4+3)
            float4 va = A4[r * (KDIM / 4) + kq0 + kq];
            float4 vb = B4[r * (KDIM / 4) + kq0 + kq];
            // With leading dim BM+1=65 (==1 mod 32), each of these four store
            // instructions covers 32 distinct banks across the warp.
            As[kq * 4 + 0][r] = va.x;
            As[kq * 4 + 1][r] = va.y;
            As[kq * 4 + 2][r] = va.z;
            As[kq * 4 + 3][r] = va.w;
            Bs[kq * 4 + 0][r] = vb.x;
            Bs[kq * 4 + 1][r] = vb.y;
            Bs[kq * 4 + 2][r] = vb.z;
            Bs[kq * 4 + 3][r] = vb.w;
        }
        __syncthreads();

        #pragma unroll
        for (int k = 0; k < BK; k++) {
            float a[4], b[4];
            #pragma unroll
            for (int i = 0; i < 4; i++) a[i] = As[k][ty * 4 + i];
            #pragma unroll
            for (int j = 0; j < 4; j++) b[j] = Bs[k][tx * 4 + j];
            #pragma unroll
            for (int i = 0; i < 4; i++)
                #pragma unroll
                for (int j = 0; j < 4; j++)
                    acc[i][j] = fmaf(a[i], b[j], acc[i][j]);
        }
        __syncthreads();
    }

    // ---- tile reductions ----
    if (tid < BM) { rowRed[tid] = 0.0f; colRed[tid] = 0.0f; }
    if (tid == 0) smaxu = 0u;
    __syncthreads();

    float lmax = -3.0e38f;
    float rs[4] = {0, 0, 0, 0};
    float cs[4] = {0, 0, 0, 0};
    #pragma unroll
    for (int i = 0; i < 4; i++) {
        #pragma unroll
        for (int j = 0; j < 4; j++) {
            float v = acc[i][j];
            lmax = fmaxf(lmax, v);
            float r = fmaxf(v, 0.0f);
            rs[i] += r;
            cs[j] += r;
        }
    }
    #pragma unroll
    for (int i = 0; i < 4; i++) {
        atomicAdd(&rowRed[ty * 4 + i], rs[i]);
        atomicAdd(&colRed[tx * 4 + i], cs[i]);
    }
    // warp max -> shared -> global
    #pragma unroll
    for (int off = 16; off > 0; off >>= 1)
        lmax = fmaxf(lmax, __shfl_xor_sync(0xFFFFFFFFu, lmax, off));
    if ((tid & 31) == 0) atomicMax(&smaxu, f2u_mono(lmax));
    __syncthreads();

    if (tid < BM) {
        atomicAdd(&g_rowsum[rowBase + tid], rowRed[tid]);
        atomicAdd(&g_colsum[colBase + tid], colRed[tid]);
    }
    if (tid == 0) atomicMax(&g_maxbits, smaxu);
}

// Bilinear resize of the two 72x72 maps to 224x224, folding in 1/max.
__global__ void simcam_resize_kernel(float* __restrict__ out) {
    int idx = blockIdx.x * blockDim.x + threadIdx.x;
    const int total = 2 * OUTH * OUTW;
    if (idx >= total) return;

    int n   = idx / (OUTH * OUTW);
    int rem = idx - n * (OUTH * OUTW);
    int oy  = rem / OUTW;
    int ox  = rem - oy * OUTW;

    const float inv = 1.0f / u2f_mono(g_maxbits);
    const float* __restrict__ map = (n == 0) ? g_rowsum : g_colsum;

    const float sy = (float)HFEAT / (float)OUTH;
    float ys = fmaxf(((float)oy + 0.5f) * sy - 0.5f, 0.0f);
    float xs = fmaxf(((float)ox + 0.5f) * sy - 0.5f, 0.0f);
    int y0 = (int)floorf(ys);
    int x0 = (int)floorf(xs);
    int y1 = min(y0 + 1, HFEAT - 1);
    int x1 = min(x0 + 1, HFEAT - 1);
    float wy = ys - (float)y0;
    float wx = xs - (float)x0;

    float a = map[y0 * HFEAT + x0];
    float b = map[y0 * HFEAT + x1];
    float c = map[y1 * HFEAT + x0];
    float d = map[y1 * HFEAT + x1];

    float v = a * (1.0f - wy) * (1.0f - wx)
            + b * (1.0f - wy) * wx
            + c * wy * (1.0f - wx)
            + d * wy * wx;
    out[idx] = v * inv;
}

extern "C" void kernel_launch(void* const* d_in, const int* in_sizes, int n_in,
                              void* d_out, int out_size)
{
    const float* x = (const float*)d_in[0];
    const float* A = x;                          // x[0]: 72*72*256
    const float* B = x + MDIM * KDIM;            // x[1]

    simcam_init_kernel<<<(MDIM + 255) / 256, 256>>>();

    dim3 grid(MDIM / BN, MDIM / BM);             // 81 x 81
    simcam_gemm_reduce_kernel<<<grid, 256>>>(A, B);

    const int total = 2 * OUTH * OUTW;
    simcam_resize_kernel<<<(total + 255) / 256, 256>>>((float*)d_out);
}

// round 10
// speedup vs baseline: 2.8857x; 2.8857x over previous
#include <cuda_runtime.h>
#include <cuda_bf16.h>
#include <cstdint>

// ---------------- problem constants ----------------
#define HFEAT 72
#define MDIM  5184            // 72*72
#define KDIM  256
#define TILE  128
#define NTILES 41             // 41*128 = 5248
#define MPAD  (NTILES * TILE) // 5248 (zero-padded rows)
#define BKC   64              // K elements per smem chunk
#define NCHUNKS (KDIM / BKC)  // 4
#define LDT   72              // padded smem row stride (bf16 elems): 144B, conflict-free
#define OUTH  224
#define OUTW  224

// ---------------- device scratch (no cudaMalloc allowed) ----------------
__device__ __align__(16) __nv_bfloat16 g_Ah[MPAD * KDIM];
__device__ __align__(16) __nv_bfloat16 g_Al[MPAD * KDIM];
__device__ __align__(16) __nv_bfloat16 g_Bh[MPAD * KDIM];
__device__ __align__(16) __nv_bfloat16 g_Bl[MPAD * KDIM];
__device__ float        g_rowsum[MDIM];
__device__ float        g_colsum[MDIM];
__device__ unsigned int g_maxbits;

// ---------------- helpers ----------------
__device__ __forceinline__ unsigned int f2u_mono(float f) {
    unsigned int b = __float_as_uint(f);
    return (b & 0x80000000u) ? ~b : (b | 0x80000000u);
}
__device__ __forceinline__ float u2f_mono(unsigned int u) {
    unsigned int b = (u & 0x80000000u) ? (u & 0x7FFFFFFFu) : ~u;
    return __uint_as_float(b);
}

// m16n8k16 row.col bf16 MMA, fp32 accum (sm_80+ baseline ISA — no 'a' target needed)
__device__ __forceinline__ void mma16816(float* c, const uint32_t* a, const uint32_t* b) {
    asm volatile(
        "mma.sync.aligned.m16n8k16.row.col.f32.bf16.bf16.f32 "
        "{%0,%1,%2,%3}, {%4,%5,%6,%7}, {%8,%9}, {%0,%1,%2,%3};"
        : "+f"(c[0]), "+f"(c[1]), "+f"(c[2]), "+f"(c[3])
        : "r"(a[0]), "r"(a[1]), "r"(a[2]), "r"(a[3]), "r"(b[0]), "r"(b[1]));
}

__device__ __forceinline__ uint32_t lds_u32(const __nv_bfloat16* p) {
    return *reinterpret_cast<const uint32_t*>(p);
}

// ---------------- kernels ----------------
__global__ void simcam_init_kernel() {
    int i = blockIdx.x * blockDim.x + threadIdx.x;
    if (i < MDIM) { g_rowsum[i] = 0.0f; g_colsum[i] = 0.0f; }
    if (i == 0) g_maxbits = 0u;
}

// fp32 -> bf16 hi/lo split, zero-padded to MPAD rows. float2 granularity.
__global__ void simcam_prep_kernel(const float* __restrict__ x) {
    const int per = MPAD * (KDIM / 2);        // float2 slots per matrix
    int idx = blockIdx.x * blockDim.x + threadIdx.x;
    if (idx >= 2 * per) return;
    int m = idx / per;
    int e = idx - m * per;
    int row = e >> 7;                          // /128 float2 per row
    int c2  = e & 127;

    float2 v = make_float2(0.0f, 0.0f);
    if (row < MDIM) {
        const float2* src = (const float2*)(x + (size_t)m * MDIM * KDIM);
        v = src[(size_t)row * 128 + c2];
    }
    __nv_bfloat16 hx = __float2bfloat16(v.x);
    __nv_bfloat16 hy = __float2bfloat16(v.y);
    __nv_bfloat16 lx = __float2bfloat16(v.x - __bfloat162float(hx));
    __nv_bfloat16 ly = __float2bfloat16(v.y - __bfloat162float(hy));

    __nv_bfloat162* Hi = (__nv_bfloat162*)(m == 0 ? g_Ah : g_Bh);
    __nv_bfloat162* Lo = (__nv_bfloat162*)(m == 0 ? g_Al : g_Bl);
    Hi[e] = __halves2bfloat162(hx, hy);
    Lo[e] = __halves2bfloat162(lx, ly);
}

// Fused mma.sync GEMM (bf16x3) + streaming relu row/col sums + global max.
// CTA: 128x128 tile, 256 threads = 8 warps (2x4), warp tile 64x32 (4x4 m16n8).
extern __shared__ __align__(16) __nv_bfloat16 dynsmem_bf16[];

__global__ __launch_bounds__(256, 2) void simcam_mma_kernel() {
    __shared__ float rowRed[TILE];
    __shared__ float colRed[TILE];

    __nv_bfloat16* sAh = dynsmem_bf16;                 // [128][LDT]
    __nv_bfloat16* sAl = sAh + TILE * LDT;
    __nv_bfloat16* sBh = sAl + TILE * LDT;
    __nv_bfloat16* sBl = sBh + TILE * LDT;

    const int tid  = threadIdx.x;
    const int wid  = tid >> 5;
    const int lane = tid & 31;
    const int g    = lane >> 2;     // group id 0..7
    const int tg   = lane & 3;      // thread-in-group 0..3
    const int wm   = wid >> 2;      // 0..1 -> warp row block (64)
    const int wn   = wid & 3;       // 0..3 -> warp col block (32)
    const int rowBase = blockIdx.y * TILE;
    const int colBase = blockIdx.x * TILE;

    if (tid < TILE) { rowRed[tid] = 0.0f; colRed[tid] = 0.0f; }

    // global operand panels as uint4 (8 bf16), 32 uint4 per 256-elem row
    const uint4* gAh = (const uint4*)g_Ah + (size_t)rowBase * 32;
    const uint4* gAl = (const uint4*)g_Al + (size_t)rowBase * 32;
    const uint4* gBh = (const uint4*)g_Bh + (size_t)colBase * 32;
    const uint4* gBl = (const uint4*)g_Bl + (size_t)colBase * 32;

    float acc[4][4][4];
    #pragma unroll
    for (int i = 0; i < 4; i++)
        #pragma unroll
        for (int j = 0; j < 4; j++)
            #pragma unroll
            for (int r = 0; r < 4; r++) acc[i][j][r] = 0.0f;

    for (int c = 0; c < NCHUNKS; c++) {
        __syncthreads();   // previous chunk's MMAs done reading smem
        // Load 128x64 bf16 tiles of all four operands (linear, padded rows).
        #pragma unroll
        for (int t = 0; t < 4; t++) {
            int idx = tid + t * 256;               // 0..1023
            int r = idx >> 3;                      // row 0..127
            int q = idx & 7;                       // uint4 (8 bf16) within 64-elem k-range
            size_t goff = (size_t)r * 32 + c * 8 + q;
            int soff = r * LDT + q * 8;            // elements; byte offset r*144+q*16 (16B aligned)
            *(uint4*)(sAh + soff) = gAh[goff];
            *(uint4*)(sAl + soff) = gAl[goff];
            *(uint4*)(sBh + soff) = gBh[goff];
            *(uint4*)(sBl + soff) = gBl[goff];
        }
        __syncthreads();

        #pragma unroll
        for (int ks = 0; ks < BKC / 16; ks++) {
            const int k0 = ks * 16 + tg * 2;
            uint32_t aH[4][4], aL[4][4], bb[4][2];

            // ---- A-hi fragments (4 m16 tiles) ----
            #pragma unroll
            for (int mt = 0; mt < 4; mt++) {
                const __nv_bfloat16* pa = sAh + (wm * 64 + mt * 16 + g) * LDT + k0;
                aH[mt][0] = lds_u32(pa);
                aH[mt][1] = lds_u32(pa + 8 * LDT);
                aH[mt][2] = lds_u32(pa + 8);
                aH[mt][3] = lds_u32(pa + 8 * LDT + 8);
            }
            // ---- B-hi fragments (4 n8 tiles) ----
            #pragma unroll
            for (int nt = 0; nt < 4; nt++) {
                const __nv_bfloat16* pb = sBh + (wn * 32 + nt * 8 + g) * LDT + k0;
                bb[nt][0] = lds_u32(pb);
                bb[nt][1] = lds_u32(pb + 8);
            }
            // Ah x Bh
            #pragma unroll
            for (int mt = 0; mt < 4; mt++)
                #pragma unroll
                for (int nt = 0; nt < 4; nt++)
                    mma16816(acc[mt][nt], aH[mt], bb[nt]);

            // ---- A-lo fragments, Al x Bh ----
            #pragma unroll
            for (int mt = 0; mt < 4; mt++) {
                const __nv_bfloat16* pa = sAl + (wm * 64 + mt * 16 + g) * LDT + k0;
                aL[mt][0] = lds_u32(pa);
                aL[mt][1] = lds_u32(pa + 8 * LDT);
                aL[mt][2] = lds_u32(pa + 8);
                aL[mt][3] = lds_u32(pa + 8 * LDT + 8);
            }
            #pragma unroll
            for (int mt = 0; mt < 4; mt++)
                #pragma unroll
                for (int nt = 0; nt < 4; nt++)
                    mma16816(acc[mt][nt], aL[mt], bb[nt]);

            // ---- B-lo fragments, Ah x Bl ----
            #pragma unroll
            for (int nt = 0; nt < 4; nt++) {
                const __nv_bfloat16* pb = sBl + (wn * 32 + nt * 8 + g) * LDT + k0;
                bb[nt][0] = lds_u32(pb);
                bb[nt][1] = lds_u32(pb + 8);
            }
            #pragma unroll
            for (int mt = 0; mt < 4; mt++)
                #pragma unroll
                for (int nt = 0; nt < 4; nt++)
                    mma16816(acc[mt][nt], aH[mt], bb[nt]);
        }
    }
    __syncthreads();

    // ---- epilogue: relu row/col sums + max ----
    // Thread owns rows {wm*64+mt*16+g, +8}, cols {wn*32+nt*8+tg*2, +1}.
    float vmax = -3.0e38f;
    #pragma unroll
    for (int mt = 0; mt < 4; mt++) {
        float r0 = 0.0f, r1 = 0.0f;
        #pragma unroll
        for (int nt = 0; nt < 4; nt++) {
            float v0 = acc[mt][nt][0], v1 = acc[mt][nt][1];
            float v2 = acc[mt][nt][2], v3 = acc[mt][nt][3];
            vmax = fmaxf(vmax, fmaxf(fmaxf(v0, v1), fmaxf(v2, v3)));
            r0 += fmaxf(v0, 0.0f) + fmaxf(v1, 0.0f);
            r1 += fmaxf(v2, 0.0f) + fmaxf(v3, 0.0f);
        }
        atomicAdd(&rowRed[wm * 64 + mt * 16 + g], r0);
        atomicAdd(&rowRed[wm * 64 + mt * 16 + g + 8], r1);
    }
    #pragma unroll
    for (int nt = 0; nt < 4; nt++) {
        float c0 = 0.0f, c1 = 0.0f;
        #pragma unroll
        for (int mt = 0; mt < 4; mt++) {
            c0 += fmaxf(acc[mt][nt][0], 0.0f) + fmaxf(acc[mt][nt][2], 0.0f);
            c1 += fmaxf(acc[mt][nt][1], 0.0f) + fmaxf(acc[mt][nt][3], 0.0f);
        }
        atomicAdd(&colRed[wn * 32 + nt * 8 + tg * 2], c0);
        atomicAdd(&colRed[wn * 32 + nt * 8 + tg * 2 + 1], c1);
    }
    // warp max -> global
    #pragma unroll
    for (int off = 16; off > 0; off >>= 1)
        vmax = fmaxf(vmax, __shfl_xor_sync(0xFFFFFFFFu, vmax, off));
    if (lane == 0) atomicMax(&g_maxbits, f2u_mono(vmax));

    __syncthreads();
    if (tid < TILE) {
        int grow = rowBase + tid;
        if (grow < MDIM) atomicAdd(&g_rowsum[grow], rowRed[tid]);
        int gcol = colBase + tid;
        if (gcol < MDIM) atomicAdd(&g_colsum[gcol], colRed[tid]);
    }
}

// Bilinear resize of the two 72x72 maps to 224x224, folding in 1/max.
__global__ void simcam_resize_kernel(float* __restrict__ out) {
    int idx = blockIdx.x * blockDim.x + threadIdx.x;
    const int total = 2 * OUTH * OUTW;
    if (idx >= total) return;

    int n   = idx / (OUTH * OUTW);
    int rem = idx - n * (OUTH * OUTW);
    int oy  = rem / OUTW;
    int ox  = rem - oy * OUTW;

    const float inv = 1.0f / u2f_mono(g_maxbits);
    const float* __restrict__ map = (n == 0) ? g_rowsum : g_colsum;

    const float sy = (float)HFEAT / (float)OUTH;
    float ys = fmaxf(((float)oy + 0.5f) * sy - 0.5f, 0.0f);
    float xs = fmaxf(((float)ox + 0.5f) * sy - 0.5f, 0.0f);
    int y0 = (int)floorf(ys);
    int x0 = (int)floorf(xs);
    int y1 = min(y0 + 1, HFEAT - 1);
    int x1 = min(x0 + 1, HFEAT - 1);
    float wy = ys - (float)y0;
    float wx = xs - (float)x0;

    float a = map[y0 * HFEAT + x0];
    float b = map[y0 * HFEAT + x1];
    float c = map[y1 * HFEAT + x0];
    float d = map[y1 * HFEAT + x1];

    float v = a * (1.0f - wy) * (1.0f - wx)
            + b * (1.0f - wy) * wx
            + c * wy * (1.0f - wx)
            + d * wy * wx;
    out[idx] = v * inv;
}

extern "C" void kernel_launch(void* const* d_in, const int* in_sizes, int n_in,
                              void* d_out, int out_size)
{
    const float* x = (const float*)d_in[0];

    const int dyn = 4 * TILE * LDT * (int)sizeof(__nv_bfloat16);  // 73728 B
    cudaFuncSetAttribute((const void*)simcam_mma_kernel,
                         cudaFuncAttributeMaxDynamicSharedMemorySize, dyn);

    simcam_init_kernel<<<(MDIM + 255) / 256, 256>>>();

    const int prep_total = 2 * MPAD * (KDIM / 2);
    simcam_prep_kernel<<<(prep_total + 255) / 256, 256>>>(x);

    dim3 grid(NTILES, NTILES);
    simcam_mma_kernel<<<grid, 256, dyn>>>();

    const int total = 2 * OUTH * OUTW;
    simcam_resize_kernel<<<(total + 255) / 256, 256>>>((float*)d_out);
}

// round 12
// speedup vs baseline: 3.0705x; 1.0640x over previous
#include <cuda_runtime.h>
#include <cuda_bf16.h>
#include <cstdint>

// ---------------- problem constants ----------------
#define HFEAT 72
#define MDIM  5184            // 72*72
#define KDIM  256
#define TILE  128
#define NTILES 41             // 41*128 = 5248
#define MPAD  (NTILES * TILE) // 5248 (zero-padded rows)
#define BKC   32              // K elements per smem chunk
#define NCHUNKS (KDIM / BKC)  // 8
#define LDT   40              // padded smem row stride (bf16): 80B; rows on distinct 16B banks
#define OPB   (TILE * LDT * 2)        // bytes per operand buffer = 10240
#define BUFB  (4 * OPB)               // bytes per chunk buffer  = 40960
#define OUTH  224
#define OUTW  224

// ---------------- device scratch (no cudaMalloc allowed) ----------------
__device__ __align__(16) __nv_bfloat16 g_Ah[MPAD * KDIM];
__device__ __align__(16) __nv_bfloat16 g_Al[MPAD * KDIM];
__device__ __align__(16) __nv_bfloat16 g_Bh[MPAD * KDIM];
__device__ __align__(16) __nv_bfloat16 g_Bl[MPAD * KDIM];
__device__ float        g_rowsum[MDIM];
__device__ float        g_colsum[MDIM];
__device__ unsigned int g_maxbits;

// ---------------- helpers ----------------
__device__ __forceinline__ unsigned int f2u_mono(float f) {
    unsigned int b = __float_as_uint(f);
    return (b & 0x80000000u) ? ~b : (b | 0x80000000u);
}
__device__ __forceinline__ float u2f_mono(unsigned int u) {
    unsigned int b = (u & 0x80000000u) ? (u & 0x7FFFFFFFu) : ~u;
    return __uint_as_float(b);
}
__device__ __forceinline__ uint32_t smem_u32(const void* p) {
    uint32_t a;
    asm("{ .reg .u64 t; cvta.to.shared.u64 t, %1; cvt.u32.u64 %0, t; }"
        : "=r"(a) : "l"(p));
    return a;
}

// m16n8k16 row.col bf16 MMA, fp32 accum (sm_80+ baseline ISA)
__device__ __forceinline__ void mma16816(float* c, const uint32_t* a, const uint32_t* b) {
    asm volatile(
        "mma.sync.aligned.m16n8k16.row.col.f32.bf16.bf16.f32 "
        "{%0,%1,%2,%3}, {%4,%5,%6,%7}, {%8,%9}, {%0,%1,%2,%3};"
        : "+f"(c[0]), "+f"(c[1]), "+f"(c[2]), "+f"(c[3])
        : "r"(a[0]), "r"(a[1]), "r"(a[2]), "r"(a[3]), "r"(b[0]), "r"(b[1]));
}
#define LDSM_X4(r, addr) \
    asm volatile("ldmatrix.sync.aligned.m8n8.x4.shared.b16 {%0,%1,%2,%3}, [%4];" \
                 : "=r"((r)[0]), "=r"((r)[1]), "=r"((r)[2]), "=r"((r)[3]) : "r"(addr))
#define LDSM_X2(r, addr) \
    asm volatile("ldmatrix.sync.aligned.m8n8.x2.shared.b16 {%0,%1}, [%2];" \
                 : "=r"((r)[0]), "=r"((r)[1]) : "r"(addr))
#define CP_ASYNC16(dst, src) \
    asm volatile("cp.async.ca.shared.global [%0], [%1], 16;" :: "r"(dst), "l"(src))
#define CP_COMMIT() asm volatile("cp.async.commit_group;" ::: "memory")
#define CP_WAIT1()  asm volatile("cp.async.wait_group 1;" ::: "memory")
#define CP_WAIT0()  asm volatile("cp.async.wait_group 0;" ::: "memory")

// ---------------- kernels ----------------
__global__ void simcam_init_kernel() {
    int i = blockIdx.x * blockDim.x + threadIdx.x;
    if (i < MDIM) { g_rowsum[i] = 0.0f; g_colsum[i] = 0.0f; }
    if (i == 0) g_maxbits = 0u;
}

// fp32 -> bf16 hi/lo split, zero-padded to MPAD rows. float2 granularity.
__global__ void simcam_prep_kernel(const float* __restrict__ x) {
    const int per = MPAD * (KDIM / 2);        // float2 slots per matrix
    int idx = blockIdx.x * blockDim.x + threadIdx.x;
    if (idx >= 2 * per) return;
    int m = idx / per;
    int e = idx - m * per;
    int row = e >> 7;                          // /128 float2 per row
    int c2  = e & 127;

    float2 v = make_float2(0.0f, 0.0f);
    if (row < MDIM) {
        const float2* src = (const float2*)(x + (size_t)m * MDIM * KDIM);
        v = src[(size_t)row * 128 + c2];
    }
    __nv_bfloat16 hx = __float2bfloat16(v.x);
    __nv_bfloat16 hy = __float2bfloat16(v.y);
    __nv_bfloat16 lx = __float2bfloat16(v.x - __bfloat162float(hx));
    __nv_bfloat16 ly = __float2bfloat16(v.y - __bfloat162float(hy));

    __nv_bfloat162* Hi = (__nv_bfloat162*)(m == 0 ? g_Ah : g_Bh);
    __nv_bfloat162* Lo = (__nv_bfloat162*)(m == 0 ? g_Al : g_Bl);
    Hi[e] = __halves2bfloat162(hx, hy);
    Lo[e] = __halves2bfloat162(lx, ly);
}

// Fused mma.sync GEMM (bf16x3) + streaming relu row/col sums + global max.
// CTA: 128x128 tile, 256 threads = 8 warps (2x4), warp tile 64x32 (4x4 m16n8).
// cp.async double-buffered K chunks of 32; fragments via ldmatrix.
extern __shared__ __align__(16) __nv_bfloat16 dynsmem_bf16[];

__global__ __launch_bounds__(256, 2) void simcam_mma_kernel() {
    __shared__ float rowRed[TILE];
    __shared__ float colRed[TILE];

    const int tid  = threadIdx.x;
    const int wid  = tid >> 5;
    const int lane = tid & 31;
    const int wm   = wid >> 2;      // 0..1 -> warp row block (64)
    const int wn   = wid & 3;       // 0..3 -> warp col block (32)
    const int rowBase = blockIdx.y * TILE;
    const int colBase = blockIdx.x * TILE;

    if (tid < TILE) { rowRed[tid] = 0.0f; colRed[tid] = 0.0f; }

    const uint32_t sbase = smem_u32(dynsmem_bf16);

    // ldmatrix lane-pattern offsets (bytes)
    // A x4: tile order rows0-7/k0, rows8-15/k0, rows0-7/k8, rows8-15/k8
    const uint32_t aoff = (uint32_t)(((lane & 7) + ((lane >> 3) & 1) * 8 + wm * 64) * (LDT * 2)
                                     + (lane >> 4) * 16);
    // B x2 (lanes mod 16): n-rows at k0 then k8
    const uint32_t boff = (uint32_t)(((lane & 7) + wn * 32) * (LDT * 2)
                                     + ((lane >> 3) & 1) * 16);

    // global operand panels as uint4 (8 bf16 = 16B); 32 u4 per 256-elem row
    const uint4* gA0 = (const uint4*)g_Ah + (size_t)rowBase * 32;
    const uint4* gA1 = (const uint4*)g_Al + (size_t)rowBase * 32;
    const uint4* gB0 = (const uint4*)g_Bh + (size_t)colBase * 32;
    const uint4* gB1 = (const uint4*)g_Bl + (size_t)colBase * 32;

    // per-thread load slots: idx = tid + i*256 -> r = idx>>2 (row), q = idx&3 (16B unit)
    const int r0 = tid >> 2,        q0 = tid & 3;
    const int r1 = (tid + 256) >> 2, q1 = tid & 3;  // +256 -> r += 64, same q

    float acc[4][4][4];
    #pragma unroll
    for (int i = 0; i < 4; i++)
        #pragma unroll
        for (int j = 0; j < 4; j++)
            #pragma unroll
            for (int r = 0; r < 4; r++) acc[i][j][r] = 0.0f;

    // ---- chunk loader (cp.async, 8 x 16B per thread) ----
    auto load_chunk = [&](int c, int b) {
        uint32_t dst = sbase + b * BUFB;
        uint32_t d0 = dst + (uint32_t)(r0 * (LDT * 2) + q0 * 16);
        uint32_t d1 = dst + (uint32_t)(r1 * (LDT * 2) + q1 * 16);
        size_t s0 = (size_t)r0 * 32 + c * 4 + q0;
        size_t s1 = (size_t)r1 * 32 + c * 4 + q1;
        CP_ASYNC16(d0,           gA0 + s0);  CP_ASYNC16(d1,           gA0 + s1);
        CP_ASYNC16(d0 + OPB,     gA1 + s0);  CP_ASYNC16(d1 + OPB,     gA1 + s1);
        CP_ASYNC16(d0 + 2 * OPB, gB0 + s0);  CP_ASYNC16(d1 + 2 * OPB, gB0 + s1);
        CP_ASYNC16(d0 + 3 * OPB, gB1 + s0);  CP_ASYNC16(d1 + 3 * OPB, gB1 + s1);
    };

    load_chunk(0, 0);
    CP_COMMIT();

    for (int c = 0; c < NCHUNKS; c++) {
        const int b = c & 1;
        if (c + 1 < NCHUNKS) {
            load_chunk(c + 1, b ^ 1);
            CP_COMMIT();
            CP_WAIT1();
        } else {
            CP_WAIT0();
        }
        __syncthreads();

        const uint32_t ah = sbase + b * BUFB + aoff;
        const uint32_t al = ah + OPB;
        const uint32_t bh = sbase + b * BUFB + 2 * OPB + boff;
        const uint32_t bl = bh + OPB;

        #pragma unroll
        for (int ks = 0; ks < BKC / 16; ks++) {
            const uint32_t kofs = ks * 32;   // 16 bf16 = 32B
            uint32_t aH[4][4], aL[4][4], bb[4][2];

            #pragma unroll
            for (int mt = 0; mt < 4; mt++) LDSM_X4(aH[mt], ah + mt * (16 * LDT * 2) + kofs);
            #pragma unroll
            for (int nt = 0; nt < 4; nt++) LDSM_X2(bb[nt], bh + nt * (8 * LDT * 2) + kofs);
            #pragma unroll
            for (int mt = 0; mt < 4; mt++)
                #pragma unroll
                for (int nt = 0; nt < 4; nt++)
                    mma16816(acc[mt][nt], aH[mt], bb[nt]);

            #pragma unroll
            for (int mt = 0; mt < 4; mt++) LDSM_X4(aL[mt], al + mt * (16 * LDT * 2) + kofs);
            #pragma unroll
            for (int mt = 0; mt < 4; mt++)
                #pragma unroll
                for (int nt = 0; nt < 4; nt++)
                    mma16816(acc[mt][nt], aL[mt], bb[nt]);

            #pragma unroll
            for (int nt = 0; nt < 4; nt++) LDSM_X2(bb[nt], bl + nt * (8 * LDT * 2) + kofs);
            #pragma unroll
            for (int mt = 0; mt < 4; mt++)
                #pragma unroll
                for (int nt = 0; nt < 4; nt++)
                    mma16816(acc[mt][nt], aH[mt], bb[nt]);
        }
        __syncthreads();   // compute done before next load overwrites this buffer
    }

    // ---- epilogue: relu row/col sums + max ----
    const int g  = lane >> 2;
    const int tg = lane & 3;
    float vmax = -3.0e38f;
    #pragma unroll
    for (int mt = 0; mt < 4; mt++) {
        float s0 = 0.0f, s1 = 0.0f;
        #pragma unroll
        for (int nt = 0; nt < 4; nt++) {
            float v0 = acc[mt][nt][0], v1 = acc[mt][nt][1];
            float v2 = acc[mt][nt][2], v3 = acc[mt][nt][3];
            vmax = fmaxf(vmax, fmaxf(fmaxf(v0, v1), fmaxf(v2, v3)));
            s0 += fmaxf(v0, 0.0f) + fmaxf(v1, 0.0f);
            s1 += fmaxf(v2, 0.0f) + fmaxf(v3, 0.0f);
        }
        atomicAdd(&rowRed[wm * 64 + mt * 16 + g], s0);
        atomicAdd(&rowRed[wm * 64 + mt * 16 + g + 8], s1);
    }
    #pragma unroll
    for (int nt = 0; nt < 4; nt++) {
        float c0 = 0.0f, c1 = 0.0f;
        #pragma unroll
        for (int mt = 0; mt < 4; mt++) {
            c0 += fmaxf(acc[mt][nt][0], 0.0f) + fmaxf(acc[mt][nt][2], 0.0f);
            c1 += fmaxf(acc[mt][nt][1], 0.0f) + fmaxf(acc[mt][nt][3], 0.0f);
        }
        atomicAdd(&colRed[wn * 32 + nt * 8 + tg * 2], c0);
        atomicAdd(&colRed[wn * 32 + nt * 8 + tg * 2 + 1], c1);
    }
    #pragma unroll
    for (int off = 16; off > 0; off >>= 1)
        vmax = fmaxf(vmax, __shfl_xor_sync(0xFFFFFFFFu, vmax, off));
    if (lane == 0) atomicMax(&g_maxbits, f2u_mono(vmax));

    __syncthreads();
    if (tid < TILE) {
        int grow = rowBase + tid;
        if (grow < MDIM) atomicAdd(&g_rowsum[grow], rowRed[tid]);
        int gcol = colBase + tid;
        if (gcol < MDIM) atomicAdd(&g_colsum[gcol], colRed[tid]);
    }
}

// Bilinear resize of the two 72x72 maps to 224x224, folding in 1/max.
__global__ void simcam_resize_kernel(float* __restrict__ out) {
    int idx = blockIdx.x * blockDim.x + threadIdx.x;
    const int total = 2 * OUTH * OUTW;
    if (idx >= total) return;

    int n   = idx / (OUTH * OUTW);
    int rem = idx - n * (OUTH * OUTW);
    int oy  = rem / OUTW;
    int ox  = rem - oy * OUTW;

    const float inv = 1.0f / u2f_mono(g_maxbits);
    const float* __restrict__ map = (n == 0) ? g_rowsum : g_colsum;

    const float sy = (float)HFEAT / (float)OUTH;
    float ys = fmaxf(((float)oy + 0.5f) * sy - 0.5f, 0.0f);
    float xs = fmaxf(((float)ox + 0.5f) * sy - 0.5f, 0.0f);
    int y0 = (int)floorf(ys);
    int x0 = (int)floorf(xs);
    int y1 = min(y0 + 1, HFEAT - 1);
    int x1 = min(x0 + 1, HFEAT - 1);
    float wy = ys - (float)y0;
    float wx = xs - (float)x0;

    float a = map[y0 * HFEAT + x0];
    float b = map[y0 * HFEAT + x1];
    float c = map[y1 * HFEAT + x0];
    float d = map[y1 * HFEAT + x1];

    float v = a * (1.0f - wy) * (1.0f - wx)
            + b * (1.0f - wy) * wx
            + c * wy * (1.0f - wx)
            + d * wy * wx;
    out[idx] = v * inv;
}

extern "C" void kernel_launch(void* const* d_in, const int* in_sizes, int n_in,
                              void* d_out, int out_size)
{
    const float* x = (const float*)d_in[0];

    const int dyn = 2 * BUFB;   // 81920 B (double-buffered chunk)
    cudaFuncSetAttribute((const void*)simcam_mma_kernel,
                         cudaFuncAttributeMaxDynamicSharedMemorySize, dyn);

    simcam_init_kernel<<<(MDIM + 255) / 256, 256>>>();

    const int prep_total = 2 * MPAD * (KDIM / 2);
    simcam_prep_kernel<<<(prep_total + 255) / 256, 256>>>(x);

    dim3 grid(NTILES, NTILES);
    simcam_mma_kernel<<<grid, 256, dyn>>>();

    const int total = 2 * OUTH * OUTW;
    simcam_resize_kernel<<<(total + 255) / 256, 256>>>((float*)d_out);
}

// round 15
// speedup vs baseline: 3.7443x; 1.2194x over previous
#include <cuda_runtime.h>
#include <cuda_bf16.h>
#include <cstdint>

// ---------------- problem constants ----------------
#define HFEAT 72
#define MDIM  5184            // 72*72
#define KDIM  256
#define TILE  128
#define NTILES 41             // 41*128 = 5248
#define MPAD  (NTILES * TILE) // 5248 (zero-padded rows)
#define BKC   32              // K elements per smem chunk
#define NCHUNKS (KDIM / BKC)  // 8
#define LDT   40              // padded smem row stride (bf16): 80B
#define OPB   (TILE * LDT * 2)        // bytes per operand buffer = 10240
#define BUFB  (3 * OPB)               // Ah, Al, Bh = 30720 B per chunk buffer
#define OUTH  224
#define OUTW  224

// ---------------- device scratch (no cudaMalloc allowed) ----------------
__device__ __align__(16) __nv_bfloat16 g_Ah[MPAD * KDIM];
__device__ __align__(16) __nv_bfloat16 g_Al[MPAD * KDIM];
__device__ __align__(16) __nv_bfloat16 g_Bh[MPAD * KDIM];
__device__ float        g_rowsum[MDIM];
__device__ float        g_colsum[MDIM];
__device__ unsigned int g_maxbits;

// ---------------- helpers ----------------
__device__ __forceinline__ unsigned int f2u_mono(float f) {
    unsigned int b = __float_as_uint(f);
    return (b & 0x80000000u) ? ~b : (b | 0x80000000u);
}
__device__ __forceinline__ float u2f_mono(unsigned int u) {
    unsigned int b = (u & 0x80000000u) ? (u & 0x7FFFFFFFu) : ~u;
    return __uint_as_float(b);
}
__device__ __forceinline__ uint32_t smem_u32(const void* p) {
    uint32_t a;
    asm("{ .reg .u64 t; cvta.to.shared.u64 t, %1; cvt.u32.u64 %0, t; }"
        : "=r"(a) : "l"(p));
    return a;
}

// m16n8k16 row.col bf16 MMA, fp32 accum (sm_80+ baseline ISA)
__device__ __forceinline__ void mma16816(float* c, const uint32_t* a, const uint32_t* b) {
    asm volatile(
        "mma.sync.aligned.m16n8k16.row.col.f32.bf16.bf16.f32 "
        "{%0,%1,%2,%3}, {%4,%5,%6,%7}, {%8,%9}, {%0,%1,%2,%3};"
        : "+f"(c[0]), "+f"(c[1]), "+f"(c[2]), "+f"(c[3])
        : "r"(a[0]), "r"(a[1]), "r"(a[2]), "r"(a[3]), "r"(b[0]), "r"(b[1]));
}
#define LDSM_X4(r, addr) \
    asm volatile("ldmatrix.sync.aligned.m8n8.x4.shared.b16 {%0,%1,%2,%3}, [%4];" \
                 : "=r"((r)[0]), "=r"((r)[1]), "=r"((r)[2]), "=r"((r)[3]) : "r"(addr))
#define LDSM_X2(r, addr) \
    asm volatile("ldmatrix.sync.aligned.m8n8.x2.shared.b16 {%0,%1}, [%2];" \
                 : "=r"((r)[0]), "=r"((r)[1]) : "r"(addr))
#define CP_ASYNC16(dst, src) \
    asm volatile("cp.async.ca.shared.global [%0], [%1], 16;" :: "r"(dst), "l"(src))
#define CP_COMMIT() asm volatile("cp.async.commit_group;" ::: "memory")
#define CP_WAIT1()  asm volatile("cp.async.wait_group 1;" ::: "memory")
#define CP_WAIT0()  asm volatile("cp.async.wait_group 0;" ::: "memory")

// ---------------- kernels ----------------
// fp32 -> bf16 hi/lo split (A) and hi (B), zero-padded to MPAD rows.
// Also zeroes the reduction scratch (replaces separate init kernel).
__global__ void simcam_prep_kernel(const float* __restrict__ x) {
    const int per = MPAD * (KDIM / 2);        // float2 slots per matrix
    int idx = blockIdx.x * blockDim.x + threadIdx.x;

    if (idx < MDIM) { g_rowsum[idx] = 0.0f; g_colsum[idx] = 0.0f; }
    if (idx == 0) g_maxbits = 0u;

    if (idx >= 2 * per) return;
    int m = idx / per;
    int e = idx - m * per;
    int row = e >> 7;                          // /128 float2 per row
    int c2  = e & 127;

    float2 v = make_float2(0.0f, 0.0f);
    if (row < MDIM) {
        const float2* src = (const float2*)(x + (size_t)m * MDIM * KDIM);
        v = src[(size_t)row * 128 + c2];
    }
    __nv_bfloat16 hx = __float2bfloat16(v.x);
    __nv_bfloat16 hy = __float2bfloat16(v.y);

    if (m == 0) {
        __nv_bfloat16 lx = __float2bfloat16(v.x - __bfloat162float(hx));
        __nv_bfloat16 ly = __float2bfloat16(v.y - __bfloat162float(hy));
        ((__nv_bfloat162*)g_Ah)[e] = __halves2bfloat162(hx, hy);
        ((__nv_bfloat162*)g_Al)[e] = __halves2bfloat162(lx, ly);
    } else {
        ((__nv_bfloat162*)g_Bh)[e] = __halves2bfloat162(hx, hy);
    }
}

// Fused mma.sync GEMM (bf16x2: Ah*Bh + Al*Bh) + relu row/col sums + global max.
// CTA: 128x128 tile, 256 threads = 8 warps (2x4), warp tile 64x32 (4x4 m16n8).
// cp.async double-buffered K chunks of 32; fragments via ldmatrix.
extern __shared__ __align__(16) __nv_bfloat16 dynsmem_bf16[];

__global__ __launch_bounds__(256, 2) void simcam_mma_kernel() {
    __shared__ float rowRed[TILE];
    __shared__ float colRed[TILE];

    const int tid  = threadIdx.x;
    const int wid  = tid >> 5;
    const int lane = tid & 31;
    const int wm   = wid >> 2;      // 0..1 -> warp row block (64)
    const int wn   = wid & 3;       // 0..3 -> warp col block (32)
    const int rowBase = blockIdx.y * TILE;
    const int colBase = blockIdx.x * TILE;

    if (tid < TILE) { rowRed[tid] = 0.0f; colRed[tid] = 0.0f; }

    const uint32_t sbase = smem_u32(dynsmem_bf16);

    // ldmatrix lane-pattern offsets (bytes)
    const uint32_t aoff = (uint32_t)(((lane & 7) + ((lane >> 3) & 1) * 8 + wm * 64) * (LDT * 2)
                                     + (lane >> 4) * 16);
    const uint32_t boff = (uint32_t)(((lane & 7) + wn * 32) * (LDT * 2)
                                     + ((lane >> 3) & 1) * 16);

    // global operand panels as uint4 (8 bf16 = 16B); 32 u4 per 256-elem row
    const uint4* gA0 = (const uint4*)g_Ah + (size_t)rowBase * 32;
    const uint4* gA1 = (const uint4*)g_Al + (size_t)rowBase * 32;
    const uint4* gB0 = (const uint4*)g_Bh + (size_t)colBase * 32;

    // per-thread load slots: idx = tid + i*256 -> r = idx>>2 (row), q = idx&3 (16B unit)
    const int r0 = tid >> 2,         q0 = tid & 3;
    const int r1 = (tid + 256) >> 2, q1 = tid & 3;  // r0+64, same q

    float acc[4][4][4];
    #pragma unroll
    for (int i = 0; i < 4; i++)
        #pragma unroll
        for (int j = 0; j < 4; j++)
            #pragma unroll
            for (int r = 0; r < 4; r++) acc[i][j][r] = 0.0f;

    // ---- chunk loader (cp.async, 6 x 16B per thread) ----
    auto load_chunk = [&](int c, int b) {
        uint32_t dst = sbase + b * BUFB;
        uint32_t d0 = dst + (uint32_t)(r0 * (LDT * 2) + q0 * 16);
        uint32_t d1 = dst + (uint32_t)(r1 * (LDT * 2) + q1 * 16);
        size_t s0 = (size_t)r0 * 32 + c * 4 + q0;
        size_t s1 = (size_t)r1 * 32 + c * 4 + q1;
        CP_ASYNC16(d0,           gA0 + s0);  CP_ASYNC16(d1,           gA0 + s1);
        CP_ASYNC16(d0 + OPB,     gA1 + s0);  CP_ASYNC16(d1 + OPB,     gA1 + s1);
        CP_ASYNC16(d0 + 2 * OPB, gB0 + s0);  CP_ASYNC16(d1 + 2 * OPB, gB0 + s1);
    };

    load_chunk(0, 0);
    CP_COMMIT();

    for (int c = 0; c < NCHUNKS; c++) {
        const int b = c & 1;
        if (c + 1 < NCHUNKS) {
            load_chunk(c + 1, b ^ 1);
            CP_COMMIT();
            CP_WAIT1();
        } else {
            CP_WAIT0();
        }
        __syncthreads();

        const uint32_t ah = sbase + b * BUFB + aoff;
        const uint32_t al = ah + OPB;
        const uint32_t bh = sbase + b * BUFB + 2 * OPB + boff;

        #pragma unroll
        for (int ks = 0; ks < BKC / 16; ks++) {
            const uint32_t kofs = ks * 32;   // 16 bf16 = 32B
            uint32_t aH[4][4], aL[4][4], bb[4][2];

            #pragma unroll
            for (int mt = 0; mt < 4; mt++) LDSM_X4(aH[mt], ah + mt * (16 * LDT * 2) + kofs);
            #pragma unroll
            for (int nt = 0; nt < 4; nt++) LDSM_X2(bb[nt], bh + nt * (8 * LDT * 2) + kofs);
            #pragma unroll
            for (int mt = 0; mt < 4; mt++)
                #pragma unroll
                for (int nt = 0; nt < 4; nt++)
                    mma16816(acc[mt][nt], aH[mt], bb[nt]);

            #pragma unroll
            for (int mt = 0; mt < 4; mt++) LDSM_X4(aL[mt], al + mt * (16 * LDT * 2) + kofs);
            #pragma unroll
            for (int mt = 0; mt < 4; mt++)
                #pragma unroll
                for (int nt = 0; nt < 4; nt++)
                    mma16816(acc[mt][nt], aL[mt], bb[nt]);
        }
        __syncthreads();   // compute done before next load overwrites this buffer
    }

    // ---- epilogue: relu row/col sums + max ----
    const int g  = lane >> 2;
    const int tg = lane & 3;
    float vmax = -3.0e38f;
    #pragma unroll
    for (int mt = 0; mt < 4; mt++) {
        float s0 = 0.0f, s1 = 0.0f;
        #pragma unroll
        for (int nt = 0; nt < 4; nt++) {
            float v0 = acc[mt][nt][0], v1 = acc[mt][nt][1];
            float v2 = acc[mt][nt][2], v3 = acc[mt][nt][3];
            vmax = fmaxf(vmax, fmaxf(fmaxf(v0, v1), fmaxf(v2, v3)));
            s0 += fmaxf(v0, 0.0f) + fmaxf(v1, 0.0f);
            s1 += fmaxf(v2, 0.0f) + fmaxf(v3, 0.0f);
        }
        atomicAdd(&rowRed[wm * 64 + mt * 16 + g], s0);
        atomicAdd(&rowRed[wm * 64 + mt * 16 + g + 8], s1);
    }
    #pragma unroll
    for (int nt = 0; nt < 4; nt++) {
        float c0 = 0.0f, c1 = 0.0f;
        #pragma unroll
        for (int mt = 0; mt < 4; mt++) {
            c0 += fmaxf(acc[mt][nt][0], 0.0f) + fmaxf(acc[mt][nt][2], 0.0f);
            c1 += fmaxf(acc[mt][nt][1], 0.0f) + fmaxf(acc[mt][nt][3], 0.0f);
        }
        atomicAdd(&colRed[wn * 32 + nt * 8 + tg * 2], c0);
        atomicAdd(&colRed[wn * 32 + nt * 8 + tg * 2 + 1], c1);
    }
    #pragma unroll
    for (int off = 16; off > 0; off >>= 1)
        vmax = fmaxf(vmax, __shfl_xor_sync(0xFFFFFFFFu, vmax, off));
    if (lane == 0) atomicMax(&g_maxbits, f2u_mono(vmax));

    __syncthreads();
    if (tid < TILE) {
        int grow = rowBase + tid;
        if (grow < MDIM) atomicAdd(&g_rowsum[grow], rowRed[tid]);
        int gcol = colBase + tid;
        if (gcol < MDIM) atomicAdd(&g_colsum[gcol], colRed[tid]);
    }
}

// Bilinear resize of the two 72x72 maps to 224x224, folding in 1/max.
__global__ void simcam_resize_kernel(float* __restrict__ out) {
    int idx = blockIdx.x * blockDim.x + threadIdx.x;
    const int total = 2 * OUTH * OUTW;
    if (idx >= total) return;

    int n   = idx / (OUTH * OUTW);
    int rem = idx - n * (OUTH * OUTW);
    int oy  = rem / OUTW;
    int ox  = rem - oy * OUTW;

    const float inv = 1.0f / u2f_mono(g_maxbits);
    const float* __restrict__ map = (n == 0) ? g_rowsum : g_colsum;

    const float sy = (float)HFEAT / (float)OUTH;
    float ys = fmaxf(((float)oy + 0.5f) * sy - 0.5f, 0.0f);
    float xs = fmaxf(((float)ox + 0.5f) * sy - 0.5f, 0.0f);
    int y0 = (int)floorf(ys);
    int x0 = (int)floorf(xs);
    int y1 = min(y0 + 1, HFEAT - 1);
    int x1 = min(x0 + 1, HFEAT - 1);
    float wy = ys - (float)y0;
    float wx = xs - (float)x0;

    float a = map[y0 * HFEAT + x0];
    float b = map[y0 * HFEAT + x1];
    float c = map[y1 * HFEAT + x0];
    float d = map[y1 * HFEAT + x1];

    float v = a * (1.0f - wy) * (1.0f - wx)
            + b * (1.0f - wy) * wx
            + c * wy * (1.0f - wx)
            + d * wy * wx;
    out[idx] = v * inv;
}

extern "C" void kernel_launch(void* const* d_in, const int* in_sizes, int n_in,
                              void* d_out, int out_size)
{
    const float* x = (const float*)d_in[0];

    const int dyn = 2 * BUFB;   // 61440 B (double-buffered 3-operand chunk)
    cudaFuncSetAttribute((const void*)simcam_mma_kernel,
                         cudaFuncAttributeMaxDynamicSharedMemorySize, dyn);

    const int prep_total = 2 * MPAD * (KDIM / 2);
    simcam_prep_kernel<<<(prep_total + 255) / 256, 256>>>(x);

    dim3 grid(NTILES, NTILES);
    simcam_mma_kernel<<<grid, 256, dyn>>>();

    const int total = 2 * OUTH * OUTW;
    simcam_resize_kernel<<<(total + 255) / 256, 256>>>((float*)d_out);
}

// round 16
// speedup vs baseline: 4.8944x; 1.3072x over previous
#include <cuda_runtime.h>
#include <cuda_bf16.h>
#include <cstdint>

// ---------------- problem constants ----------------
#define HFEAT 72
#define MDIM  5184            // 72*72
#define KDIM  256
#define TILE  128
#define NTILES 41             // 41*128 = 5248
#define MPAD  (NTILES * TILE) // 5248 (zero-padded rows)
#define BKC   32              // K elements per smem chunk
#define NCHUNKS (KDIM / BKC)  // 8
#define LDT   40              // padded smem row stride (bf16): 80B
#define OPB   (TILE * LDT * 2)        // bytes per operand buffer = 10240
#define BUFB  (2 * OPB)               // A, B = 20480 B per chunk buffer
#define OUTH  224
#define OUTW  224

// ---------------- device scratch (no cudaMalloc allowed) ----------------
__device__ __align__(16) __nv_bfloat16 g_A[MPAD * KDIM];
__device__ __align__(16) __nv_bfloat16 g_B[MPAD * KDIM];
__device__ float        g_rowsum[MDIM];
__device__ float        g_colsum[MDIM];
__device__ unsigned int g_maxbits;

// ---------------- helpers ----------------
__device__ __forceinline__ unsigned int f2u_mono(float f) {
    unsigned int b = __float_as_uint(f);
    return (b & 0x80000000u) ? ~b : (b | 0x80000000u);
}
__device__ __forceinline__ float u2f_mono(unsigned int u) {
    unsigned int b = (u & 0x80000000u) ? (u & 0x7FFFFFFFu) : ~u;
    return __uint_as_float(b);
}
__device__ __forceinline__ uint32_t smem_u32(const void* p) {
    uint32_t a;
    asm("{ .reg .u64 t; cvta.to.shared.u64 t, %1; cvt.u32.u64 %0, t; }"
        : "=r"(a) : "l"(p));
    return a;
}

// m16n8k16 row.col bf16 MMA, fp32 accum (sm_80+ baseline ISA)
__device__ __forceinline__ void mma16816(float* c, const uint32_t* a, const uint32_t* b) {
    asm volatile(
        "mma.sync.aligned.m16n8k16.row.col.f32.bf16.bf16.f32 "
        "{%0,%1,%2,%3}, {%4,%5,%6,%7}, {%8,%9}, {%0,%1,%2,%3};"
        : "+f"(c[0]), "+f"(c[1]), "+f"(c[2]), "+f"(c[3])
        : "r"(a[0]), "r"(a[1]), "r"(a[2]), "r"(a[3]), "r"(b[0]), "r"(b[1]));
}
#define LDSM_X4(r, addr) \
    asm volatile("ldmatrix.sync.aligned.m8n8.x4.shared.b16 {%0,%1,%2,%3}, [%4];" \
                 : "=r"((r)[0]), "=r"((r)[1]), "=r"((r)[2]), "=r"((r)[3]) : "r"(addr))
#define LDSM_X2(r, addr) \
    asm volatile("ldmatrix.sync.aligned.m8n8.x2.shared.b16 {%0,%1}, [%2];" \
                 : "=r"((r)[0]), "=r"((r)[1]) : "r"(addr))
#define CP_ASYNC16(dst, src) \
    asm volatile("cp.async.ca.shared.global [%0], [%1], 16;" :: "r"(dst), "l"(src))
#define CP_COMMIT() asm volatile("cp.async.commit_group;" ::: "memory")
#define CP_WAIT1()  asm volatile("cp.async.wait_group 1;" ::: "memory")
#define CP_WAIT0()  asm volatile("cp.async.wait_group 0;" ::: "memory")

// ---------------- kernels ----------------
// fp32 -> bf16 conversion (both matrices), zero-padded to MPAD rows.
// Also zeroes the reduction scratch.
__global__ void simcam_prep_kernel(const float* __restrict__ x) {
    const int per = MPAD * (KDIM / 2);        // float2 slots per matrix
    int idx = blockIdx.x * blockDim.x + threadIdx.x;

    if (idx < MDIM) { g_rowsum[idx] = 0.0f; g_colsum[idx] = 0.0f; }
    if (idx == 0) g_maxbits = 0u;

    if (idx >= 2 * per) return;
    int m = idx / per;
    int e = idx - m * per;
    int row = e >> 7;                          // /128 float2 per row
    int c2  = e & 127;

    float2 v = make_float2(0.0f, 0.0f);
    if (row < MDIM) {
        const float2* src = (const float2*)(x + (size_t)m * MDIM * KDIM);
        v = src[(size_t)row * 128 + c2];
    }
    __nv_bfloat162 h = __halves2bfloat162(__float2bfloat16(v.x), __float2bfloat16(v.y));
    ((__nv_bfloat162*)(m == 0 ? g_A : g_B))[e] = h;
}

// Fused mma.sync GEMM (bf16x1) + relu row/col sums + global max.
// CTA: 128x128 tile, 256 threads = 8 warps (2x4), warp tile 64x32 (4x4 m16n8).
// cp.async double-buffered K chunks of 32; fragments via ldmatrix.
extern __shared__ __align__(16) __nv_bfloat16 dynsmem_bf16[];

__global__ __launch_bounds__(256, 2) void simcam_mma_kernel() {
    __shared__ float rowRed[TILE];
    __shared__ float colRed[TILE];

    const int tid  = threadIdx.x;
    const int wid  = tid >> 5;
    const int lane = tid & 31;
    const int wm   = wid >> 2;      // 0..1 -> warp row block (64)
    const int wn   = wid & 3;       // 0..3 -> warp col block (32)
    const int rowBase = blockIdx.y * TILE;
    const int colBase = blockIdx.x * TILE;

    if (tid < TILE) { rowRed[tid] = 0.0f; colRed[tid] = 0.0f; }

    const uint32_t sbase = smem_u32(dynsmem_bf16);

    // ldmatrix lane-pattern offsets (bytes)
    const uint32_t aoff = (uint32_t)(((lane & 7) + ((lane >> 3) & 1) * 8 + wm * 64) * (LDT * 2)
                                     + (lane >> 4) * 16);
    const uint32_t boff = (uint32_t)(((lane & 7) + wn * 32) * (LDT * 2)
                                     + ((lane >> 3) & 1) * 16);

    // global operand panels as uint4 (8 bf16 = 16B); 32 u4 per 256-elem row
    const uint4* gA = (const uint4*)g_A + (size_t)rowBase * 32;
    const uint4* gB = (const uint4*)g_B + (size_t)colBase * 32;

    // per-thread load slots: idx = tid + i*256 -> r = idx>>2 (row), q = idx&3 (16B unit)
    const int r0 = tid >> 2,         q0 = tid & 3;
    const int r1 = (tid + 256) >> 2, q1 = tid & 3;  // r0+64, same q

    float acc[4][4][4];
    #pragma unroll
    for (int i = 0; i < 4; i++)
        #pragma unroll
        for (int j = 0; j < 4; j++)
            #pragma unroll
            for (int r = 0; r < 4; r++) acc[i][j][r] = 0.0f;

    // ---- chunk loader (cp.async, 4 x 16B per thread) ----
    auto load_chunk = [&](int c, int b) {
        uint32_t dst = sbase + b * BUFB;
        uint32_t d0 = dst + (uint32_t)(r0 * (LDT * 2) + q0 * 16);
        uint32_t d1 = dst + (uint32_t)(r1 * (LDT * 2) + q1 * 16);
        size_t s0 = (size_t)r0 * 32 + c * 4 + q0;
        size_t s1 = (size_t)r1 * 32 + c * 4 + q1;
        CP_ASYNC16(d0,       gA + s0);  CP_ASYNC16(d1,       gA + s1);
        CP_ASYNC16(d0 + OPB, gB + s0);  CP_ASYNC16(d1 + OPB, gB + s1);
    };

    load_chunk(0, 0);
    CP_COMMIT();

    for (int c = 0; c < NCHUNKS; c++) {
        const int b = c & 1;
        if (c + 1 < NCHUNKS) {
            load_chunk(c + 1, b ^ 1);
            CP_COMMIT();
            CP_WAIT1();
        } else {
            CP_WAIT0();
        }
        __syncthreads();

        const uint32_t ah = sbase + b * BUFB + aoff;
        const uint32_t bh = sbase + b * BUFB + OPB + boff;

        #pragma unroll
        for (int ks = 0; ks < BKC / 16; ks++) {
            const uint32_t kofs = ks * 32;   // 16 bf16 = 32B
            uint32_t aH[4][4], bb[4][2];

            #pragma unroll
            for (int mt = 0; mt < 4; mt++) LDSM_X4(aH[mt], ah + mt * (16 * LDT * 2) + kofs);
            #pragma unroll
            for (int nt = 0; nt < 4; nt++) LDSM_X2(bb[nt], bh + nt * (8 * LDT * 2) + kofs);
            #pragma unroll
            for (int mt = 0; mt < 4; mt++)
                #pragma unroll
                for (int nt = 0; nt < 4; nt++)
                    mma16816(acc[mt][nt], aH[mt], bb[nt]);
        }
        __syncthreads();   // compute done before next load overwrites this buffer
    }

    // ---- epilogue: relu row/col sums + max ----
    const int g  = lane >> 2;
    const int tg = lane & 3;
    float vmax = -3.0e38f;
    #pragma unroll
    for (int mt = 0; mt < 4; mt++) {
        float s0 = 0.0f, s1 = 0.0f;
        #pragma unroll
        for (int nt = 0; nt < 4; nt++) {
            float v0 = acc[mt][nt][0], v1 = acc[mt][nt][1];
            float v2 = acc[mt][nt][2], v3 = acc[mt][nt][3];
            vmax = fmaxf(vmax, fmaxf(fmaxf(v0, v1), fmaxf(v2, v3)));
            s0 += fmaxf(v0, 0.0f) + fmaxf(v1, 0.0f);
            s1 += fmaxf(v2, 0.0f) + fmaxf(v3, 0.0f);
        }
        atomicAdd(&rowRed[wm * 64 + mt * 16 + g], s0);
        atomicAdd(&rowRed[wm * 64 + mt * 16 + g + 8], s1);
    }
    #pragma unroll
    for (int nt = 0; nt < 4; nt++) {
        float c0 = 0.0f, c1 = 0.0f;
        #pragma unroll
        for (int mt = 0; mt < 4; mt++) {
            c0 += fmaxf(acc[mt][nt][0], 0.0f) + fmaxf(acc[mt][nt][2], 0.0f);
            c1 += fmaxf(acc[mt][nt][1], 0.0f) + fmaxf(acc[mt][nt][3], 0.0f);
        }
        atomicAdd(&colRed[wn * 32 + nt * 8 + tg * 2], c0);
        atomicAdd(&colRed[wn * 32 + nt * 8 + tg * 2 + 1], c1);
    }
    #pragma unroll
    for (int off = 16; off > 0; off >>= 1)
        vmax = fmaxf(vmax, __shfl_xor_sync(0xFFFFFFFFu, vmax, off));
    if (lane == 0) atomicMax(&g_maxbits, f2u_mono(vmax));

    __syncthreads();
    if (tid < TILE) {
        int grow = rowBase + tid;
        if (grow < MDIM) atomicAdd(&g_rowsum[grow], rowRed[tid]);
        int gcol = colBase + tid;
        if (gcol < MDIM) atomicAdd(&g_colsum[gcol], colRed[tid]);
    }
}

// Bilinear resize of the two 72x72 maps to 224x224, folding in 1/max.
__global__ void simcam_resize_kernel(float* __restrict__ out) {
    int idx = blockIdx.x * blockDim.x + threadIdx.x;
    const int total = 2 * OUTH * OUTW;
    if (idx >= total) return;

    int n   = idx / (OUTH * OUTW);
    int rem = idx - n * (OUTH * OUTW);
    int oy  = rem / OUTW;
    int ox  = rem - oy * OUTW;

    const float inv = 1.0f / u2f_mono(g_maxbits);
    const float* __restrict__ map = (n == 0) ? g_rowsum : g_colsum;

    const float sy = (float)HFEAT / (float)OUTH;
    float ys = fmaxf(((float)oy + 0.5f) * sy - 0.5f, 0.0f);
    float xs = fmaxf(((float)ox + 0.5f) * sy - 0.5f, 0.0f);
    int y0 = (int)floorf(ys);
    int x0 = (int)floorf(xs);
    int y1 = min(y0 + 1, HFEAT - 1);
    int x1 = min(x0 + 1, HFEAT - 1);
    float wy = ys - (float)y0;
    float wx = xs - (float)x0;

    float a = map[y0 * HFEAT + x0];
    float b = map[y0 * HFEAT + x1];
    float c = map[y1 * HFEAT + x0];
    float d = map[y1 * HFEAT + x1];

    float v = a * (1.0f - wy) * (1.0f - wx)
            + b * (1.0f - wy) * wx
            + c * wy * (1.0f - wx)
            + d * wy * wx;
    out[idx] = v * inv;
}

extern "C" void kernel_launch(void* const* d_in, const int* in_sizes, int n_in,
                              void* d_out, int out_size)
{
    const float* x = (const float*)d_in[0];

    const int dyn = 2 * BUFB;   // 40960 B (double-buffered 2-operand chunk)
    cudaFuncSetAttribute((const void*)simcam_mma_kernel,
                         cudaFuncAttributeMaxDynamicSharedMemorySize, dyn);

    const int prep_total = 2 * MPAD * (KDIM / 2);
    simcam_prep_kernel<<<(prep_total + 255) / 256, 256>>>(x);

    dim3 grid(NTILES, NTILES);
    simcam_mma_kernel<<<grid, 256, dyn>>>();

    const int total = 2 * OUTH * OUTW;
    simcam_resize_kernel<<<(total + 255) / 256, 256>>>((float*)d_out);
}

// round 17
// speedup vs baseline: 8.1599x; 1.6672x over previous
#include <cuda_runtime.h>
#include <cuda_bf16.h>
#include <cstdint>

// ---------------- problem constants ----------------
#define HFEAT 72
#define MDIM  5184            // 72*72
#define KDIM  256
#define TILE  128
#define NTILES 41             // 41*128 = 5248
#define MPAD  (NTILES * TILE) // 5248 (zero-padded rows)
#define BKC   32              // K elements per smem chunk
#define NCHUNKS (KDIM / BKC)  // 8
#define NSTAGE 3
#define LDT   40              // padded smem row stride (bf16): 80B
#define OPB   (TILE * LDT * 2)        // bytes per operand buffer = 10240
#define BUFB  (2 * OPB)               // A, B = 20480 B per chunk buffer
#define OUTH  224
#define OUTW  224

// ---------------- device scratch (no cudaMalloc allowed) ----------------
__device__ __align__(16) __nv_bfloat16 g_A[MPAD * KDIM];
__device__ __align__(16) __nv_bfloat16 g_B[MPAD * KDIM];
__device__ float        g_rowsum[MDIM];
__device__ float        g_colsum[MDIM];
__device__ unsigned int g_maxbits;

// ---------------- helpers ----------------
__device__ __forceinline__ unsigned int f2u_mono(float f) {
    unsigned int b = __float_as_uint(f);
    return (b & 0x80000000u) ? ~b : (b | 0x80000000u);
}
__device__ __forceinline__ float u2f_mono(unsigned int u) {
    unsigned int b = (u & 0x80000000u) ? (u & 0x7FFFFFFFu) : ~u;
    return __uint_as_float(b);
}
__device__ __forceinline__ uint32_t smem_u32(const void* p) {
    uint32_t a;
    asm("{ .reg .u64 t; cvta.to.shared.u64 t, %1; cvt.u32.u64 %0, t; }"
        : "=r"(a) : "l"(p));
    return a;
}

// m16n8k16 row.col bf16 MMA, fp32 accum (sm_80+ baseline ISA)
__device__ __forceinline__ void mma16816(float* c, const uint32_t* a, const uint32_t* b) {
    asm volatile(
        "mma.sync.aligned.m16n8k16.row.col.f32.bf16.bf16.f32 "
        "{%0,%1,%2,%3}, {%4,%5,%6,%7}, {%8,%9}, {%0,%1,%2,%3};"
        : "+f"(c[0]), "+f"(c[1]), "+f"(c[2]), "+f"(c[3])
        : "r"(a[0]), "r"(a[1]), "r"(a[2]), "r"(a[3]), "r"(b[0]), "r"(b[1]));
}
#define LDSM_X4(r, addr) \
    asm volatile("ldmatrix.sync.aligned.m8n8.x4.shared.b16 {%0,%1,%2,%3}, [%4];" \
                 : "=r"((r)[0]), "=r"((r)[1]), "=r"((r)[2]), "=r"((r)[3]) : "r"(addr))
#define LDSM_X2(r, addr) \
    asm volatile("ldmatrix.sync.aligned.m8n8.x2.shared.b16 {%0,%1}, [%2];" \
                 : "=r"((r)[0]), "=r"((r)[1]) : "r"(addr))
#define CP_ASYNC16(dst, src) \
    asm volatile("cp.async.ca.shared.global [%0], [%1], 16;" :: "r"(dst), "l"(src))
#define CP_COMMIT() asm volatile("cp.async.commit_group;" ::: "memory")
#define CP_WAIT1()  asm volatile("cp.async.wait_group 1;" ::: "memory")
#define CP_WAIT0()  asm volatile("cp.async.wait_group 0;" ::: "memory")

// ---------------- kernels ----------------
// fp32 -> bf16 conversion (both matrices), zero-padded to MPAD rows.
// Also zeroes the reduction scratch.
__global__ void simcam_prep_kernel(const float* __restrict__ x) {
    const int per = MPAD * (KDIM / 2);        // float2 slots per matrix
    int idx = blockIdx.x * blockDim.x + threadIdx.x;

    if (idx < MDIM) { g_rowsum[idx] = 0.0f; g_colsum[idx] = 0.0f; }
    if (idx == 0) g_maxbits = 0u;

    if (idx >= 2 * per) return;
    int m = idx / per;
    int e = idx - m * per;
    int row = e >> 7;                          // /128 float2 per row
    int c2  = e & 127;

    float2 v = make_float2(0.0f, 0.0f);
    if (row < MDIM) {
        const float2* src = (const float2*)(x + (size_t)m * MDIM * KDIM);
        v = src[(size_t)row * 128 + c2];
    }
    __nv_bfloat162 h = __halves2bfloat162(__float2bfloat16(v.x), __float2bfloat16(v.y));
    ((__nv_bfloat162*)(m == 0 ? g_A : g_B))[e] = h;
}

// Fused mma.sync GEMM (bf16x1) + relu row/col sums + global max.
// CTA: 128x128 tile, 256 threads = 8 warps (2x4), warp tile 64x32 (4x4 m16n8).
// 3-stage cp.async pipeline, ONE __syncthreads per chunk; shfl-tree epilogue.
extern __shared__ __align__(16) __nv_bfloat16 dynsmem_bf16[];

__global__ __launch_bounds__(256, 2) void simcam_mma_kernel() {
    const int tid  = threadIdx.x;
    const int lane = tid & 31;
    const int wid  = tid >> 5;
    const int wm   = wid >> 2;      // 0..1 -> warp row block (64)
    const int wn   = wid & 3;       // 0..3 -> warp col block (32)
    const int g    = lane >> 2;     // 0..7
    const int tg   = lane & 3;      // 0..3
    const int rowBase = blockIdx.y * TILE;
    const int colBase = blockIdx.x * TILE;

    const uint32_t sbase = smem_u32(dynsmem_bf16);

    // ldmatrix lane-pattern offsets (bytes)
    const uint32_t aoff = (uint32_t)(((lane & 7) + ((lane >> 3) & 1) * 8 + wm * 64) * (LDT * 2)
                                     + (lane >> 4) * 16);
    const uint32_t boff = (uint32_t)(((lane & 7) + wn * 32) * (LDT * 2)
                                     + ((lane >> 3) & 1) * 16);

    // global operand panels as uint4 (8 bf16 = 16B); 32 u4 per 256-elem row
    const uint4* gA = (const uint4*)g_A + (size_t)rowBase * 32;
    const uint4* gB = (const uint4*)g_B + (size_t)colBase * 32;

    // per-thread load slots
    const int r0 = tid >> 2,         q0 = tid & 3;
    const int r1 = (tid + 256) >> 2, q1 = tid & 3;  // r0+64, same q

    float acc[4][4][4];
    #pragma unroll
    for (int i = 0; i < 4; i++)
        #pragma unroll
        for (int j = 0; j < 4; j++)
            #pragma unroll
            for (int r = 0; r < 4; r++) acc[i][j][r] = 0.0f;

    // ---- chunk loader (cp.async, 4 x 16B per thread) ----
    auto load_chunk = [&](int c, int b) {
        uint32_t dst = sbase + b * BUFB;
        uint32_t d0 = dst + (uint32_t)(r0 * (LDT * 2) + q0 * 16);
        uint32_t d1 = dst + (uint32_t)(r1 * (LDT * 2) + q1 * 16);
        size_t s0 = (size_t)r0 * 32 + c * 4 + q0;
        size_t s1 = (size_t)r1 * 32 + c * 4 + q1;
        CP_ASYNC16(d0,       gA + s0);  CP_ASYNC16(d1,       gA + s1);
        CP_ASYNC16(d0 + OPB, gB + s0);  CP_ASYNC16(d1 + OPB, gB + s1);
    };

    // prologue: two chunks in flight
    load_chunk(0, 0); CP_COMMIT();
    load_chunk(1, 1); CP_COMMIT();

    for (int c = 0; c < NCHUNKS; c++) {
        const int b = c % NSTAGE;
        if (c + 1 < NCHUNKS) { CP_WAIT1(); } else { CP_WAIT0(); }
        __syncthreads();   // chunk c visible CTA-wide; all warps done with buffer (c-1)%3

        const uint32_t ah = sbase + b * BUFB + aoff;
        const uint32_t bh = sbase + b * BUFB + OPB + boff;

        #pragma unroll
        for (int ks = 0; ks < BKC / 16; ks++) {
            const uint32_t kofs = ks * 32;   // 16 bf16 = 32B
            uint32_t aH[4][4], bb[4][2];

            #pragma unroll
            for (int mt = 0; mt < 4; mt++) LDSM_X4(aH[mt], ah + mt * (16 * LDT * 2) + kofs);
            #pragma unroll
            for (int nt = 0; nt < 4; nt++) LDSM_X2(bb[nt], bh + nt * (8 * LDT * 2) + kofs);
            #pragma unroll
            for (int mt = 0; mt < 4; mt++)
                #pragma unroll
                for (int nt = 0; nt < 4; nt++)
                    mma16816(acc[mt][nt], aH[mt], bb[nt]);
        }

        // issue next-next chunk into buffer (c+2)%3 == (c-1)%3 (safe per sync induction)
        if (c + 2 < NCHUNKS) { load_chunk(c + 2, (c + 2) % NSTAGE); CP_COMMIT(); }
    }

    // ---- epilogue: shfl-tree reductions -> direct global atomics ----
    float vmax = -3.0e38f;
    #pragma unroll
    for (int mt = 0; mt < 4; mt++) {
        float s0 = 0.0f, s1 = 0.0f;
        #pragma unroll
        for (int nt = 0; nt < 4; nt++) {
            float v0 = acc[mt][nt][0], v1 = acc[mt][nt][1];
            float v2 = acc[mt][nt][2], v3 = acc[mt][nt][3];
            vmax = fmaxf(vmax, fmaxf(fmaxf(v0, v1), fmaxf(v2, v3)));
            s0 += fmaxf(v0, 0.0f) + fmaxf(v1, 0.0f);
            s1 += fmaxf(v2, 0.0f) + fmaxf(v3, 0.0f);
        }
        // reduce across tg (lane bits 0,1): all 4 col-groups of this row
        s0 += __shfl_xor_sync(0xFFFFFFFFu, s0, 1);
        s0 += __shfl_xor_sync(0xFFFFFFFFu, s0, 2);
        s1 += __shfl_xor_sync(0xFFFFFFFFu, s1, 1);
        s1 += __shfl_xor_sync(0xFFFFFFFFu, s1, 2);
        if (tg == 0) {
            int r = rowBase + wm * 64 + mt * 16 + g;
            if (r < MDIM) atomicAdd(&g_rowsum[r], s0);
            if (r + 8 < MDIM) atomicAdd(&g_rowsum[r + 8], s1);
        }
    }
    #pragma unroll
    for (int nt = 0; nt < 4; nt++) {
        float c0 = 0.0f, c1 = 0.0f;
        #pragma unroll
        for (int mt = 0; mt < 4; mt++) {
            c0 += fmaxf(acc[mt][nt][0], 0.0f) + fmaxf(acc[mt][nt][2], 0.0f);
            c1 += fmaxf(acc[mt][nt][1], 0.0f) + fmaxf(acc[mt][nt][3], 0.0f);
        }
        // reduce across g (lane bits 2,3,4): all 8 row-groups of this col
        c0 += __shfl_xor_sync(0xFFFFFFFFu, c0, 4);
        c0 += __shfl_xor_sync(0xFFFFFFFFu, c0, 8);
        c0 += __shfl_xor_sync(0xFFFFFFFFu, c0, 16);
        c1 += __shfl_xor_sync(0xFFFFFFFFu, c1, 4);
        c1 += __shfl_xor_sync(0xFFFFFFFFu, c1, 8);
        c1 += __shfl_xor_sync(0xFFFFFFFFu, c1, 16);
        if (g == 0) {
            int col = colBase + wn * 32 + nt * 8 + tg * 2;
            if (col < MDIM) atomicAdd(&g_colsum[col], c0);
            if (col + 1 < MDIM) atomicAdd(&g_colsum[col + 1], c1);
        }
    }
    #pragma unroll
    for (int off = 16; off > 0; off >>= 1)
        vmax = fmaxf(vmax, __shfl_xor_sync(0xFFFFFFFFu, vmax, off));
    if (lane == 0) atomicMax(&g_maxbits, f2u_mono(vmax));
}

// Bilinear resize of the two 72x72 maps to 224x224, folding in 1/max.
__global__ void simcam_resize_kernel(float* __restrict__ out) {
    int idx = blockIdx.x * blockDim.x + threadIdx.x;
    const int total = 2 * OUTH * OUTW;
    if (idx >= total) return;

    int n   = idx / (OUTH * OUTW);
    int rem = idx - n * (OUTH * OUTW);
    int oy  = rem / OUTW;
    int ox  = rem - oy * OUTW;

    const float inv = 1.0f / u2f_mono(g_maxbits);
    const float* __restrict__ map = (n == 0) ? g_rowsum : g_colsum;

    const float sy = (float)HFEAT / (float)OUTH;
    float ys = fmaxf(((float)oy + 0.5f) * sy - 0.5f, 0.0f);
    float xs = fmaxf(((float)ox + 0.5f) * sy - 0.5f, 0.0f);
    int y0 = (int)floorf(ys);
    int x0 = (int)floorf(xs);
    int y1 = min(y0 + 1, HFEAT - 1);
    int x1 = min(x0 + 1, HFEAT - 1);
    float wy = ys - (float)y0;
    float wx = xs - (float)x0;

    float a = map[y0 * HFEAT + x0];
    float b = map[y0 * HFEAT + x1];
    float c = map[y1 * HFEAT + x0];
    float d = map[y1 * HFEAT + x1];

    float v = a * (1.0f - wy) * (1.0f - wx)
            + b * (1.0f - wy) * wx
            + c * wy * (1.0f - wx)
            + d * wy * wx;
    out[idx] = v * inv;
}

extern "C" void kernel_launch(void* const* d_in, const int* in_sizes, int n_in,
                              void* d_out, int out_size)
{
    const float* x = (const float*)d_in[0];

    const int dyn = NSTAGE * BUFB;   // 61440 B (3-stage 2-operand chunks)
    cudaFuncSetAttribute((const void*)simcam_mma_kernel,
                         cudaFuncAttributeMaxDynamicSharedMemorySize, dyn);

    const int prep_total = 2 * MPAD * (KDIM / 2);
    simcam_prep_kernel<<<(prep_total + 255) / 256, 256>>>(x);

    dim3 grid(NTILES, NTILES);
    simcam_mma_kernel<<<grid, 256, dyn>>>();

    const int total = 2 * OUTH * OUTW;
    simcam_resize_kernel<<<(total + 255) / 256, 256>>>((float*)d_out);
}